// round 1
// baseline (speedup 1.0000x reference)
#include <cuda_runtime.h>
#include <math.h>

// Problem constants
#define BATCH 2
#define SEQ 2048
#define DM 2048
#define NH 16
#define HD 128
#define NQKV ((NH + 2*NH) * HD)   // 6144
#define NTOK (BATCH * SEQ)        // 4096

// Scratch (allocation-free rule: __device__ globals)
__device__ float g_qkv[(size_t)NTOK * NQKV];       // 96 MB
__device__ float g_attn[(size_t)NTOK * (NH * HD)]; // 32 MB

// ---------------------------------------------------------------------------
// Classic 128x128x8 SGEMM, 256 threads, 8x8 per-thread microtile.
// C[M,N] = A[M,K] * B[K,N], all row-major, M%128==0, N%128==0, K%8==0.
// ---------------------------------------------------------------------------
__global__ __launch_bounds__(256) void sgemm_kernel(
    const float* __restrict__ A, const float* __restrict__ B,
    float* __restrict__ C, int M, int N, int K)
{
    __shared__ float As[8][128];
    __shared__ float Bs[8][128];

    const int tid = threadIdx.x;
    const int bx = blockIdx.x;   // N tile
    const int by = blockIdx.y;   // M tile
    const int tx = tid & 15;
    const int ty = tid >> 4;

    const float* Ab = A + (size_t)(by * 128) * K;
    const float* Bb = B + (size_t)(bx * 128);

    const int aRow = tid >> 1;            // 0..127
    const int aCol = (tid & 1) * 4;       // 0 or 4
    const int bRow = tid >> 5;            // 0..7
    const int bCol = (tid & 31) * 4;      // 0..124

    float acc[8][8];
#pragma unroll
    for (int i = 0; i < 8; i++)
#pragma unroll
        for (int j = 0; j < 8; j++) acc[i][j] = 0.f;

    for (int k0 = 0; k0 < K; k0 += 8) {
        float4 av = *(const float4*)(Ab + (size_t)aRow * K + k0 + aCol);
        float4 bv = *(const float4*)(Bb + (size_t)(k0 + bRow) * N + bCol);
        __syncthreads();   // previous compute done before overwrite
        As[aCol + 0][aRow] = av.x;
        As[aCol + 1][aRow] = av.y;
        As[aCol + 2][aRow] = av.z;
        As[aCol + 3][aRow] = av.w;
        *(float4*)&Bs[bRow][bCol] = bv;
        __syncthreads();

#pragma unroll
        for (int kk = 0; kk < 8; kk++) {
            float4 a0 = *(const float4*)&As[kk][ty * 8];
            float4 a1 = *(const float4*)&As[kk][ty * 8 + 4];
            float4 b0 = *(const float4*)&Bs[kk][tx * 8];
            float4 b1 = *(const float4*)&Bs[kk][tx * 8 + 4];
            float ar[8] = {a0.x, a0.y, a0.z, a0.w, a1.x, a1.y, a1.z, a1.w};
            float br[8] = {b0.x, b0.y, b0.z, b0.w, b1.x, b1.y, b1.z, b1.w};
#pragma unroll
            for (int i = 0; i < 8; i++)
#pragma unroll
                for (int j = 0; j < 8; j++)
                    acc[i][j] = fmaf(ar[i], br[j], acc[i][j]);
        }
    }

#pragma unroll
    for (int i = 0; i < 8; i++) {
        float* crow = C + (size_t)(by * 128 + ty * 8 + i) * N + bx * 128 + tx * 8;
        float4 v0 = make_float4(acc[i][0], acc[i][1], acc[i][2], acc[i][3]);
        float4 v1 = make_float4(acc[i][4], acc[i][5], acc[i][6], acc[i][7]);
        *(float4*)crow = v0;
        *(float4*)(crow + 4) = v1;
    }
}

// ---------------------------------------------------------------------------
// RoPE in-place on q and k heads of g_qkv.
// grid: (NTOK, 32) heads 0..15 = q, 16..31 = k (contiguous in qkv layout).
// ---------------------------------------------------------------------------
__global__ void rope_kernel(float* __restrict__ qkv,
                            const float* __restrict__ cosp,
                            const float* __restrict__ sinp)
{
    const int t = blockIdx.x;         // token 0..4095
    const int hh = blockIdx.y;        // 0..31
    const int d = threadIdx.x;        // 0..63
    const int s = t & (SEQ - 1);

    float* p = qkv + (size_t)t * NQKV + hh * HD;
    float x1 = p[d];
    float x2 = p[d + 64];
    float c1 = cosp[s * HD + d];
    float c2 = cosp[s * HD + d + 64];
    float s1 = sinp[s * HD + d];
    float s2 = sinp[s * HD + d + 64];
    p[d]      = x1 * c1 - x2 * s1;   // x1*cos + (-x2)*sin
    p[d + 64] = x2 * c2 + x1 * s2;   // x2*cos + ( x1)*sin
}

// ---------------------------------------------------------------------------
// Flash attention, fp32. BQ=BK=32, HD=128, 128 threads.
// grid: (SEQ/32, BATCH*NH). K and V share one smem buffer (serial use).
// Output layout: g_attn[t][h*128 + d]  (i.e. [b, s, h*hd]).
// ---------------------------------------------------------------------------
#define BQ 32
#define BKV 32
#define PADW 132   // floats per padded row (128 + 4)

__global__ __launch_bounds__(128) void flash_kernel(
    const float* __restrict__ qkv, float* __restrict__ out)
{
    __shared__ float Qs[BQ][PADW];
    __shared__ float KVs[BKV][PADW];
    __shared__ float Sm[BQ][BKV + 1];
    __shared__ float mS[BQ], lS[BQ], alphaS[BQ];

    const int tid = threadIdx.x;        // 0..127
    const int bh = blockIdx.y;          // 0..31
    const int b = bh >> 4;
    const int h = bh & 15;
    const int q0 = blockIdx.x * BQ;
    const float scale = 0.08838834764831845f;  // 1/sqrt(128)

    const float* qbase = qkv + (size_t)(b * SEQ + q0) * NQKV + h * HD;
    const float* kbase = qkv + (size_t)(b * SEQ) * NQKV + (NH + h) * HD;
    const float* vbase = qkv + (size_t)(b * SEQ) * NQKV + (2 * NH + h) * HD;

    // Load Q tile (scaled)
    for (int i = tid; i < BQ * 32; i += 128) {
        int r = i >> 5, c4 = i & 31;
        float4 v = *(const float4*)(qbase + (size_t)r * NQKV + c4 * 4);
        v.x *= scale; v.y *= scale; v.z *= scale; v.w *= scale;
        *(float4*)&Qs[r][c4 * 4] = v;
    }
    if (tid < BQ) { mS[tid] = -INFINITY; lS[tid] = 0.f; }

    const int r = tid >> 2;   // output row 0..31
    const int g = tid & 3;    // column group
    float acc[32];            // O cols: float4 chunks c4 = g + 4*cc
#pragma unroll
    for (int i = 0; i < 32; i++) acc[i] = 0.f;

    __syncthreads();

    for (int kt = 0; kt < SEQ / BKV; kt++) {
        // ---- load K tile ----
        for (int i = tid; i < BKV * 32; i += 128) {
            int rr = i >> 5, c4 = i & 31;
            *(float4*)&KVs[rr][c4 * 4] =
                *(const float4*)(kbase + (size_t)(kt * BKV + rr) * NQKV + c4 * 4);
        }
        __syncthreads();

        // ---- S = Q K^T : thread -> S[r][g + 4*jj] ----
        {
            float s[8];
#pragma unroll
            for (int jj = 0; jj < 8; jj++) s[jj] = 0.f;
#pragma unroll 4
            for (int k4 = 0; k4 < 32; k4++) {
                float4 q = *(const float4*)&Qs[r][k4 * 4];
#pragma unroll
                for (int jj = 0; jj < 8; jj++) {
                    int j = g + 4 * jj;
                    float4 kv = *(const float4*)&KVs[j][k4 * 4];
                    s[jj] += q.x * kv.x + q.y * kv.y + q.z * kv.z + q.w * kv.w;
                }
            }
#pragma unroll
            for (int jj = 0; jj < 8; jj++) Sm[r][g + 4 * jj] = s[jj];
        }
        __syncthreads();

        // ---- online softmax: one thread per row ----
        if (tid < BQ) {
            int rr = tid;
            float m_old = mS[rr];
            float m = m_old;
#pragma unroll
            for (int j = 0; j < BKV; j++) m = fmaxf(m, Sm[rr][j]);
            float alpha = __expf(m_old - m);
            float l = lS[rr] * alpha;
#pragma unroll
            for (int j = 0; j < BKV; j++) {
                float p = __expf(Sm[rr][j] - m);
                Sm[rr][j] = p;
                l += p;
            }
            mS[rr] = m; lS[rr] = l; alphaS[rr] = alpha;
        }
        __syncthreads();

        // ---- load V tile over KVs ----
        for (int i = tid; i < BKV * 32; i += 128) {
            int rr = i >> 5, c4 = i & 31;
            *(float4*)&KVs[rr][c4 * 4] =
                *(const float4*)(vbase + (size_t)(kt * BKV + rr) * NQKV + c4 * 4);
        }
        float alpha = alphaS[r];
#pragma unroll
        for (int i = 0; i < 32; i++) acc[i] *= alpha;
        __syncthreads();

        // ---- O += P V ----
#pragma unroll 4
        for (int j = 0; j < BKV; j++) {
            float p = Sm[r][j];
#pragma unroll
            for (int cc = 0; cc < 8; cc++) {
                int c4 = g + 4 * cc;
                float4 v = *(const float4*)&KVs[j][c4 * 4];
                acc[cc * 4 + 0] = fmaf(p, v.x, acc[cc * 4 + 0]);
                acc[cc * 4 + 1] = fmaf(p, v.y, acc[cc * 4 + 1]);
                acc[cc * 4 + 2] = fmaf(p, v.z, acc[cc * 4 + 2]);
                acc[cc * 4 + 3] = fmaf(p, v.w, acc[cc * 4 + 3]);
            }
        }
        __syncthreads();
    }

    // ---- epilogue: normalize and write ----
    float linv = 1.0f / lS[r];
    float* obase = out + (size_t)(b * SEQ + q0 + r) * (NH * HD) + h * HD;
#pragma unroll
    for (int cc = 0; cc < 8; cc++) {
        int c4 = g + 4 * cc;
        float4 v = make_float4(acc[cc * 4 + 0] * linv, acc[cc * 4 + 1] * linv,
                               acc[cc * 4 + 2] * linv, acc[cc * 4 + 3] * linv);
        *(float4*)(obase + c4 * 4) = v;
    }
}

// ---------------------------------------------------------------------------
extern "C" void kernel_launch(void* const* d_in, const int* in_sizes, int n_in,
                              void* d_out, int out_size)
{
    const float* hidden = (const float*)d_in[0];   // [B,S,DM]
    const float* cosp   = (const float*)d_in[1];   // [S,HD]
    const float* sinp   = (const float*)d_in[2];   // [S,HD]
    const float* wqkv   = (const float*)d_in[3];   // [DM, NQKV]
    const float* wo     = (const float*)d_in[4];   // [NH*HD, DM]
    float* out = (float*)d_out;                    // [B,S,DM]

    void* qkv_ptr = nullptr;
    void* attn_ptr = nullptr;
    cudaGetSymbolAddress(&qkv_ptr, g_qkv);
    cudaGetSymbolAddress(&attn_ptr, g_attn);
    float* qkv = (float*)qkv_ptr;
    float* attn = (float*)attn_ptr;

    // 1) QKV projection: [4096,2048] x [2048,6144]
    {
        dim3 grid(NQKV / 128, NTOK / 128);  // 48 x 32
        sgemm_kernel<<<grid, 256>>>(hidden, wqkv, qkv, NTOK, NQKV, DM);
    }
    // 2) RoPE on q,k heads in-place
    {
        dim3 grid(NTOK, 2 * NH);
        rope_kernel<<<grid, 64>>>(qkv, cosp, sinp);
    }
    // 3) Flash attention
    {
        dim3 grid(SEQ / BQ, BATCH * NH);    // 64 x 32
        flash_kernel<<<grid, 128>>>(qkv, attn);
    }
    // 4) Output projection: [4096,2048] x [2048,2048]
    {
        dim3 grid(DM / 128, NTOK / 128);    // 16 x 32
        sgemm_kernel<<<grid, 256>>>(attn, wo, out, NTOK, DM, NH * HD);
    }
}

// round 2
// speedup vs baseline: 3.1450x; 3.1450x over previous
#include <cuda_runtime.h>
#include <math.h>

// Problem constants
#define BATCH 2
#define SEQ 2048
#define DM 2048
#define NH 16
#define HD 128
#define NQKV ((NH + 2*NH) * HD)   // 6144
#define NTOK (BATCH * SEQ)        // 4096

// Scratch (allocation-free rule: __device__ globals)
__device__ float g_qkv[(size_t)NTOK * NQKV];       // 96 MB
__device__ float g_attn[(size_t)NTOK * (NH * HD)]; // 32 MB

// ---------------------------------------------------------------------------
// TF32 helpers
// ---------------------------------------------------------------------------
__device__ __forceinline__ unsigned cvt_tf32(float x) {
    unsigned u;
    asm("cvt.rna.tf32.f32 %0, %1;" : "=r"(u) : "f"(x));
    return u;
}

// D += A(16x8, row) * B(8x8, col)  tf32 inputs, f32 accum
__device__ __forceinline__ void mma_m16n8k8(float* c, const unsigned* a, const unsigned* b) {
    asm volatile(
        "mma.sync.aligned.m16n8k8.row.col.f32.tf32.tf32.f32 "
        "{%0,%1,%2,%3}, {%4,%5,%6,%7}, {%8,%9}, {%0,%1,%2,%3};"
        : "+f"(c[0]), "+f"(c[1]), "+f"(c[2]), "+f"(c[3])
        : "r"(a[0]), "r"(a[1]), "r"(a[2]), "r"(a[3]), "r"(b[0]), "r"(b[1]));
}

// ---------------------------------------------------------------------------
// TF32 GEMM: C[M,N] = A[M,K]*B[K,N], row-major. M%128==0, N%128==0, K%32==0.
// 256 threads, block tile 128x128x32, warp tile 64x32, mma m16n8k8.
// ---------------------------------------------------------------------------
#define ASTR 36
#define BSTR 136

__global__ __launch_bounds__(256) void gemm_tf32(
    const float* __restrict__ A, const float* __restrict__ B,
    float* __restrict__ C, int M, int N, int K)
{
    __shared__ unsigned As[128 * ASTR];   // A[row][k], stride 36
    __shared__ unsigned Bs[32 * BSTR];    // B[k][col], stride 136

    const int tid = threadIdx.x;
    const int wid = tid >> 5;
    const int lane = tid & 31;
    const int g = lane >> 2;     // group
    const int t = lane & 3;      // thread in group
    const int warp_m = wid & 1;  // 0..1  (64 rows)
    const int warp_n = wid >> 1; // 0..3  (32 cols)

    const float* Ab = A + (size_t)(blockIdx.y * 128) * K;
    const float* Bb = B + (size_t)(blockIdx.x * 128);

    const int arow = tid >> 3;          // 0..31 (stride 32 over p)
    const int acol = (tid & 7) * 4;     // 0..28
    const int brow = tid >> 5;          // 0..7 (stride 8 over p)
    const int bcol = (tid & 31) * 4;    // 0..124

    float acc[4][4][4];
#pragma unroll
    for (int mi = 0; mi < 4; mi++)
#pragma unroll
        for (int nj = 0; nj < 4; nj++)
#pragma unroll
            for (int r = 0; r < 4; r++) acc[mi][nj][r] = 0.f;

    float4 aStage[4], bStage[4];

    // prologue: load ktile 0
#pragma unroll
    for (int p = 0; p < 4; p++) {
        aStage[p] = *(const float4*)(Ab + (size_t)(arow + p * 32) * K + acol);
        bStage[p] = *(const float4*)(Bb + (size_t)(brow + p * 8) * N + bcol);
    }
#pragma unroll
    for (int p = 0; p < 4; p++) {
        float4 v = aStage[p];
        uint4 u = make_uint4(cvt_tf32(v.x), cvt_tf32(v.y), cvt_tf32(v.z), cvt_tf32(v.w));
        *(uint4*)&As[(arow + p * 32) * ASTR + acol] = u;
        float4 w = bStage[p];
        uint4 x = make_uint4(cvt_tf32(w.x), cvt_tf32(w.y), cvt_tf32(w.z), cvt_tf32(w.w));
        *(uint4*)&Bs[(brow + p * 8) * BSTR + bcol] = x;
    }
    __syncthreads();

    const int KT = K >> 5;
    for (int kt = 0; kt < KT; kt++) {
        // prefetch next tile into regs
        if (kt + 1 < KT) {
            int k0 = (kt + 1) * 32;
#pragma unroll
            for (int p = 0; p < 4; p++) {
                aStage[p] = *(const float4*)(Ab + (size_t)(arow + p * 32) * K + k0 + acol);
                bStage[p] = *(const float4*)(Bb + (size_t)(k0 + brow + p * 8) * N + bcol);
            }
        }

        // compute on current smem tile
#pragma unroll
        for (int ks = 0; ks < 4; ks++) {
            const int kk = ks * 8;
            unsigned afr[4][4], bfr[4][2];
#pragma unroll
            for (int mi = 0; mi < 4; mi++) {
                int rb = warp_m * 64 + mi * 16;
                afr[mi][0] = As[(rb + g) * ASTR + kk + t];
                afr[mi][1] = As[(rb + g + 8) * ASTR + kk + t];
                afr[mi][2] = As[(rb + g) * ASTR + kk + t + 4];
                afr[mi][3] = As[(rb + g + 8) * ASTR + kk + t + 4];
            }
#pragma unroll
            for (int nj = 0; nj < 4; nj++) {
                int cb = warp_n * 32 + nj * 8;
                bfr[nj][0] = Bs[(kk + t) * BSTR + cb + g];
                bfr[nj][1] = Bs[(kk + t + 4) * BSTR + cb + g];
            }
#pragma unroll
            for (int mi = 0; mi < 4; mi++)
#pragma unroll
                for (int nj = 0; nj < 4; nj++)
                    mma_m16n8k8(acc[mi][nj], afr[mi], bfr[nj]);
        }
        __syncthreads();

        if (kt + 1 < KT) {
#pragma unroll
            for (int p = 0; p < 4; p++) {
                float4 v = aStage[p];
                uint4 u = make_uint4(cvt_tf32(v.x), cvt_tf32(v.y), cvt_tf32(v.z), cvt_tf32(v.w));
                *(uint4*)&As[(arow + p * 32) * ASTR + acol] = u;
                float4 w = bStage[p];
                uint4 x = make_uint4(cvt_tf32(w.x), cvt_tf32(w.y), cvt_tf32(w.z), cvt_tf32(w.w));
                *(uint4*)&Bs[(brow + p * 8) * BSTR + bcol] = x;
            }
            __syncthreads();
        }
    }

    // epilogue
#pragma unroll
    for (int mi = 0; mi < 4; mi++) {
#pragma unroll
        for (int nj = 0; nj < 4; nj++) {
            int r0 = blockIdx.y * 128 + warp_m * 64 + mi * 16 + g;
            int c0 = blockIdx.x * 128 + warp_n * 32 + nj * 8 + 2 * t;
            *(float2*)(C + (size_t)r0 * N + c0) = make_float2(acc[mi][nj][0], acc[mi][nj][1]);
            *(float2*)(C + (size_t)(r0 + 8) * N + c0) = make_float2(acc[mi][nj][2], acc[mi][nj][3]);
        }
    }
}

// ---------------------------------------------------------------------------
// RoPE in-place on q and k heads of g_qkv.
// ---------------------------------------------------------------------------
__global__ void rope_kernel(float* __restrict__ qkv,
                            const float* __restrict__ cosp,
                            const float* __restrict__ sinp)
{
    const int tk = blockIdx.x;
    const int hh = blockIdx.y;
    const int d = threadIdx.x;
    const int s = tk & (SEQ - 1);

    float* p = qkv + (size_t)tk * NQKV + hh * HD;
    float x1 = p[d];
    float x2 = p[d + 64];
    float c1 = cosp[s * HD + d];
    float c2 = cosp[s * HD + d + 64];
    float s1 = sinp[s * HD + d];
    float s2 = sinp[s * HD + d + 64];
    p[d]      = x1 * c1 - x2 * s1;
    p[d + 64] = x2 * c2 + x1 * s2;
}

// ---------------------------------------------------------------------------
// Flash attention with TF32 mma. BQ=BKV=64, HD=128, 256 threads (8 warps).
// S phase: warp grid 4x2 (16 Q-rows x 32 KV-cols per warp).
// PV phase: warp grid 2x4 (32 rows x 32 HD-cols per warp).
// ---------------------------------------------------------------------------
#define QSTR 132
#define SSTR 68
#define FLASH_SMEM ((64*QSTR*3 + 64*SSTR) * 4 + 64*3*4)

__global__ __launch_bounds__(256) void flash_tf32(
    const float* __restrict__ qkv, float* __restrict__ out)
{
    extern __shared__ unsigned sh[];
    unsigned* Qs = sh;                    // [64][132] tf32 bits
    unsigned* Ks = Qs + 64 * QSTR;        // [64][132]
    unsigned* Vs = Ks + 64 * QSTR;        // [64][132]
    unsigned* Sm = Vs + 64 * QSTR;        // [64][68]  f32 scores -> tf32 P
    float* mS = (float*)(Sm + 64 * SSTR);
    float* lS = mS + 64;
    float* aS = lS + 64;

    const int tid = threadIdx.x;
    const int wid = tid >> 5;
    const int lane = tid & 31;
    const int g = lane >> 2;
    const int t = lane & 3;

    const int b = blockIdx.y >> 4;
    const int h = blockIdx.y & 15;
    const int q0 = blockIdx.x * 64;
    const float scale = 0.08838834764831845f;  // 1/sqrt(128)

    const float* qbase = qkv + (size_t)(b * SEQ + q0) * NQKV + h * HD;
    const float* kbase = qkv + (size_t)(b * SEQ) * NQKV + (NH + h) * HD;
    const float* vbase = qkv + (size_t)(b * SEQ) * NQKV + (2 * NH + h) * HD;

    // load Q (scaled, tf32)
#pragma unroll 2
    for (int i = tid; i < 64 * 32; i += 256) {
        int r = i >> 5, c4 = (i & 31) * 4;
        float4 v = *(const float4*)(qbase + (size_t)r * NQKV + c4);
        uint4 u = make_uint4(cvt_tf32(v.x * scale), cvt_tf32(v.y * scale),
                             cvt_tf32(v.z * scale), cvt_tf32(v.w * scale));
        *(uint4*)&Qs[r * QSTR + c4] = u;
    }
    if (tid < 64) { mS[tid] = -INFINITY; lS[tid] = 0.f; }

    float oacc[2][4][4];
#pragma unroll
    for (int mi = 0; mi < 2; mi++)
#pragma unroll
        for (int nj = 0; nj < 4; nj++)
#pragma unroll
            for (int r = 0; r < 4; r++) oacc[mi][nj][r] = 0.f;

    const int sm_rb = (wid >> 1) * 16;   // S-phase row base
    const int sm_cb = (wid & 1) * 32;    // S-phase col base
    const int pm = wid >> 2;             // PV-phase row base /32
    const int pn = wid & 3;              // PV-phase col base /32

    __syncthreads();

    for (int kt = 0; kt < SEQ / 64; kt++) {
        // ---- load K and V tiles ----
#pragma unroll 2
        for (int i = tid; i < 64 * 32; i += 256) {
            int r = i >> 5, c4 = (i & 31) * 4;
            float4 kv = *(const float4*)(kbase + (size_t)(kt * 64 + r) * NQKV + c4);
            uint4 ku = make_uint4(cvt_tf32(kv.x), cvt_tf32(kv.y), cvt_tf32(kv.z), cvt_tf32(kv.w));
            *(uint4*)&Ks[r * QSTR + c4] = ku;
            float4 vv = *(const float4*)(vbase + (size_t)(kt * 64 + r) * NQKV + c4);
            uint4 vu = make_uint4(cvt_tf32(vv.x), cvt_tf32(vv.y), cvt_tf32(vv.z), cvt_tf32(vv.w));
            *(uint4*)&Vs[r * QSTR + c4] = vu;
        }
        __syncthreads();

        // ---- S = Q K^T ----
        {
            float sacc[4][4];
#pragma unroll
            for (int nj = 0; nj < 4; nj++)
#pragma unroll
                for (int r = 0; r < 4; r++) sacc[nj][r] = 0.f;

#pragma unroll
            for (int ks = 0; ks < 16; ks++) {
                const int kk = ks * 8;
                unsigned qa[4], kb[4][2];
                qa[0] = Qs[(sm_rb + g) * QSTR + kk + t];
                qa[1] = Qs[(sm_rb + g + 8) * QSTR + kk + t];
                qa[2] = Qs[(sm_rb + g) * QSTR + kk + t + 4];
                qa[3] = Qs[(sm_rb + g + 8) * QSTR + kk + t + 4];
#pragma unroll
                for (int nj = 0; nj < 4; nj++) {
                    int cb = sm_cb + nj * 8;
                    kb[nj][0] = Ks[(cb + g) * QSTR + kk + t];
                    kb[nj][1] = Ks[(cb + g) * QSTR + kk + t + 4];
                }
#pragma unroll
                for (int nj = 0; nj < 4; nj++)
                    mma_m16n8k8(sacc[nj], qa, kb[nj]);
            }
            // write raw scores to Sm (f32 bits)
#pragma unroll
            for (int nj = 0; nj < 4; nj++) {
                int col = sm_cb + nj * 8 + 2 * t;
                Sm[(sm_rb + g) * SSTR + col]     = __float_as_uint(sacc[nj][0]);
                Sm[(sm_rb + g) * SSTR + col + 1] = __float_as_uint(sacc[nj][1]);
                Sm[(sm_rb + g + 8) * SSTR + col]     = __float_as_uint(sacc[nj][2]);
                Sm[(sm_rb + g + 8) * SSTR + col + 1] = __float_as_uint(sacc[nj][3]);
            }
        }
        __syncthreads();

        // ---- online softmax: 4 threads per row ----
        {
            const int row = tid >> 2;
            const int part = tid & 3;
            float mold = mS[row];
            float vals[16];
            float mloc = -INFINITY;
#pragma unroll
            for (int j = 0; j < 16; j++) {
                vals[j] = __uint_as_float(Sm[row * SSTR + part * 16 + j]);
                mloc = fmaxf(mloc, vals[j]);
            }
            mloc = fmaxf(mloc, __shfl_xor_sync(0xffffffffu, mloc, 1));
            mloc = fmaxf(mloc, __shfl_xor_sync(0xffffffffu, mloc, 2));
            float mnew = fmaxf(mold, mloc);
            float alpha = __expf(mold - mnew);
            float ps = 0.f;
#pragma unroll
            for (int j = 0; j < 16; j++) {
                float p = __expf(vals[j] - mnew);
                ps += p;
                Sm[row * SSTR + part * 16 + j] = cvt_tf32(p);
            }
            ps += __shfl_xor_sync(0xffffffffu, ps, 1);
            ps += __shfl_xor_sync(0xffffffffu, ps, 2);
            if (part == 0) {
                mS[row] = mnew;
                lS[row] = lS[row] * alpha + ps;
                aS[row] = alpha;
            }
        }
        __syncthreads();

        // ---- rescale O, then O += P V ----
#pragma unroll
        for (int mi = 0; mi < 2; mi++) {
            int r0 = pm * 32 + mi * 16 + g;
            float al0 = aS[r0];
            float al1 = aS[r0 + 8];
#pragma unroll
            for (int nj = 0; nj < 4; nj++) {
                oacc[mi][nj][0] *= al0;
                oacc[mi][nj][1] *= al0;
                oacc[mi][nj][2] *= al1;
                oacc[mi][nj][3] *= al1;
            }
        }
#pragma unroll
        for (int ks = 0; ks < 8; ks++) {
            const int kk = ks * 8;
            unsigned pa[2][4], vb[4][2];
#pragma unroll
            for (int mi = 0; mi < 2; mi++) {
                int rb = pm * 32 + mi * 16;
                pa[mi][0] = Sm[(rb + g) * SSTR + kk + t];
                pa[mi][1] = Sm[(rb + g + 8) * SSTR + kk + t];
                pa[mi][2] = Sm[(rb + g) * SSTR + kk + t + 4];
                pa[mi][3] = Sm[(rb + g + 8) * SSTR + kk + t + 4];
            }
#pragma unroll
            for (int nj = 0; nj < 4; nj++) {
                int cb = pn * 32 + nj * 8;
                vb[nj][0] = Vs[(kk + t) * QSTR + cb + g];
                vb[nj][1] = Vs[(kk + t + 4) * QSTR + cb + g];
            }
#pragma unroll
            for (int mi = 0; mi < 2; mi++)
#pragma unroll
                for (int nj = 0; nj < 4; nj++)
                    mma_m16n8k8(oacc[mi][nj], pa[mi], vb[nj]);
        }
        __syncthreads();
    }

    // ---- epilogue: normalize + write [token][h*HD + col] ----
#pragma unroll
    for (int mi = 0; mi < 2; mi++) {
        int r0 = pm * 32 + mi * 16 + g;
        float li0 = 1.0f / lS[r0];
        float li1 = 1.0f / lS[r0 + 8];
#pragma unroll
        for (int nj = 0; nj < 4; nj++) {
            int col = pn * 32 + nj * 8 + 2 * t;
            float* o0 = out + (size_t)(b * SEQ + q0 + r0) * (NH * HD) + h * HD + col;
            float* o1 = out + (size_t)(b * SEQ + q0 + r0 + 8) * (NH * HD) + h * HD + col;
            *(float2*)o0 = make_float2(oacc[mi][nj][0] * li0, oacc[mi][nj][1] * li0);
            *(float2*)o1 = make_float2(oacc[mi][nj][2] * li1, oacc[mi][nj][3] * li1);
        }
    }
}

// ---------------------------------------------------------------------------
extern "C" void kernel_launch(void* const* d_in, const int* in_sizes, int n_in,
                              void* d_out, int out_size)
{
    const float* hidden = (const float*)d_in[0];
    const float* cosp   = (const float*)d_in[1];
    const float* sinp   = (const float*)d_in[2];
    const float* wqkv   = (const float*)d_in[3];
    const float* wo     = (const float*)d_in[4];
    float* out = (float*)d_out;

    void* qkv_ptr = nullptr;
    void* attn_ptr = nullptr;
    cudaGetSymbolAddress(&qkv_ptr, g_qkv);
    cudaGetSymbolAddress(&attn_ptr, g_attn);
    float* qkv = (float*)qkv_ptr;
    float* attn = (float*)attn_ptr;

    static bool attr_set = false;
    if (!attr_set) {
        cudaFuncSetAttribute(flash_tf32, cudaFuncAttributeMaxDynamicSharedMemorySize, FLASH_SMEM);
        attr_set = true;
    }

    // 1) QKV projection: [4096,2048] x [2048,6144]
    {
        dim3 grid(NQKV / 128, NTOK / 128);
        gemm_tf32<<<grid, 256>>>(hidden, wqkv, qkv, NTOK, NQKV, DM);
    }
    // 2) RoPE
    {
        dim3 grid(NTOK, 2 * NH);
        rope_kernel<<<grid, 64>>>(qkv, cosp, sinp);
    }
    // 3) Flash attention (tf32 mma)
    {
        dim3 grid(SEQ / 64, BATCH * NH);
        flash_tf32<<<grid, 256, FLASH_SMEM>>>(qkv, attn);
    }
    // 4) Output projection: [4096,2048] x [2048,2048]
    {
        dim3 grid(DM / 128, NTOK / 128);
        gemm_tf32<<<grid, 256>>>(attn, wo, out, NTOK, DM, NH * HD);
    }
}

// round 3
// speedup vs baseline: 4.4247x; 1.4069x over previous
#include <cuda_runtime.h>
#include <math.h>

// Problem constants
#define BATCH 2
#define SEQ 2048
#define DM 2048
#define NH 16
#define HD 128
#define NQKV ((NH + 2*NH) * HD)   // 6144
#define NTOK (BATCH * SEQ)        // 4096

// Scratch (allocation-free rule: __device__ globals)
__device__ float g_qkv[(size_t)NTOK * NQKV];        // 96 MB
__device__ float g_attn[(size_t)NTOK * (NH * HD)];  // 32 MB
__device__ float g_hid_t[(size_t)NTOK * DM];        // 32 MB (tf32-rounded hidden)
__device__ float g_wqkv_t[(size_t)DM * NQKV];       // 48 MB
__device__ float g_wo_t[(size_t)DM * DM];           // 16 MB

// ---------------------------------------------------------------------------
// helpers
// ---------------------------------------------------------------------------
__device__ __forceinline__ unsigned cvt_tf32(float x) {
    unsigned u;
    asm("cvt.rna.tf32.f32 %0, %1;" : "=r"(u) : "f"(x));
    return u;
}
__device__ __forceinline__ float rnd_tf32(float x) {
    return __uint_as_float(cvt_tf32(x));
}

__device__ __forceinline__ void mma_m16n8k8(float* c, const unsigned* a, const unsigned* b) {
    asm volatile(
        "mma.sync.aligned.m16n8k8.row.col.f32.tf32.tf32.f32 "
        "{%0,%1,%2,%3}, {%4,%5,%6,%7}, {%8,%9}, {%0,%1,%2,%3};"
        : "+f"(c[0]), "+f"(c[1]), "+f"(c[2]), "+f"(c[3])
        : "r"(a[0]), "r"(a[1]), "r"(a[2]), "r"(a[3]), "r"(b[0]), "r"(b[1]));
}

__device__ __forceinline__ void cp16(void* dst_smem, const void* src) {
    unsigned d = (unsigned)__cvta_generic_to_shared(dst_smem);
    asm volatile("cp.async.cg.shared.global [%0], [%1], 16;" :: "r"(d), "l"(src));
}
__device__ __forceinline__ void cp_commit() {
    asm volatile("cp.async.commit_group;");
}
template<int N>
__device__ __forceinline__ void cp_wait() {
    asm volatile("cp.async.wait_group %0;" :: "n"(N));
}

// ---------------------------------------------------------------------------
// tf32 pre-rounding (vectorized)
// ---------------------------------------------------------------------------
__global__ void round_tf32_kernel(const float4* __restrict__ in,
                                  float4* __restrict__ out, int n4)
{
    int i = blockIdx.x * 256 + threadIdx.x;
    if (i < n4) {
        float4 v = in[i];
        out[i] = make_float4(rnd_tf32(v.x), rnd_tf32(v.y), rnd_tf32(v.z), rnd_tf32(v.w));
    }
}

// ---------------------------------------------------------------------------
// TF32 GEMM: C = A*B, A,B pre-rounded to tf32. 128x128x32 tile, cp.async
// 3-stage pipeline, 256 threads, 2 CTAs/SM.
// ---------------------------------------------------------------------------
#define ASTR 36
#define BSTR 136
#define STG_W (128*ASTR + 32*BSTR)   // 8960 words / stage
#define GEMM_SMEM (3 * STG_W * 4)    // 107520 bytes

__global__ __launch_bounds__(256, 2) void gemm_tf32(
    const float* __restrict__ A, const float* __restrict__ B,
    float* __restrict__ C, int M, int N, int K)
{
    extern __shared__ float sm[];

    const int tid = threadIdx.x;
    const int wid = tid >> 5;
    const int lane = tid & 31;
    const int g = lane >> 2;
    const int t = lane & 3;
    const int warp_m = wid & 1;
    const int warp_n = wid >> 1;

    const float* Ab = A + (size_t)(blockIdx.y * 128) * K;
    const float* Bb = B + (size_t)(blockIdx.x * 128);

    const int arow = tid >> 3;          // 0..31
    const int acol = (tid & 7) * 4;
    const int brow = tid >> 5;          // 0..7
    const int bcol = (tid & 31) * 4;

    float acc[4][4][4];
#pragma unroll
    for (int mi = 0; mi < 4; mi++)
#pragma unroll
        for (int nj = 0; nj < 4; nj++)
#pragma unroll
            for (int r = 0; r < 4; r++) acc[mi][nj][r] = 0.f;

    const int KT = K >> 5;

#define GEMM_ISSUE(stage, kt)                                                       \
    do {                                                                            \
        float* as_ = sm + (stage) * STG_W;                                          \
        float* bs_ = as_ + 128 * ASTR;                                              \
        int k0_ = (kt) * 32;                                                        \
        _Pragma("unroll")                                                           \
        for (int p = 0; p < 4; p++) {                                               \
            cp16(&as_[(arow + p * 32) * ASTR + acol],                               \
                 Ab + (size_t)(arow + p * 32) * K + k0_ + acol);                    \
            cp16(&bs_[(brow + p * 8) * BSTR + bcol],                                \
                 Bb + (size_t)(k0_ + brow + p * 8) * N + bcol);                     \
        }                                                                           \
    } while (0)

    GEMM_ISSUE(0, 0); cp_commit();
    GEMM_ISSUE(1, 1); cp_commit();

    for (int kt = 0; kt < KT; kt++) {
        cp_wait<1>();
        __syncthreads();

        if (kt + 2 < KT) GEMM_ISSUE((kt + 2) % 3, kt + 2);
        cp_commit();

        const float* as = sm + (kt % 3) * STG_W;
        const float* bs = as + 128 * ASTR;

#pragma unroll
        for (int ks = 0; ks < 4; ks++) {
            const int kk = ks * 8;
            unsigned afr[4][4], bfr[4][2];
#pragma unroll
            for (int mi = 0; mi < 4; mi++) {
                int rb = warp_m * 64 + mi * 16;
                afr[mi][0] = __float_as_uint(as[(rb + g) * ASTR + kk + t]);
                afr[mi][1] = __float_as_uint(as[(rb + g + 8) * ASTR + kk + t]);
                afr[mi][2] = __float_as_uint(as[(rb + g) * ASTR + kk + t + 4]);
                afr[mi][3] = __float_as_uint(as[(rb + g + 8) * ASTR + kk + t + 4]);
            }
#pragma unroll
            for (int nj = 0; nj < 4; nj++) {
                int cb = warp_n * 32 + nj * 8;
                bfr[nj][0] = __float_as_uint(bs[(kk + t) * BSTR + cb + g]);
                bfr[nj][1] = __float_as_uint(bs[(kk + t + 4) * BSTR + cb + g]);
            }
#pragma unroll
            for (int mi = 0; mi < 4; mi++)
#pragma unroll
                for (int nj = 0; nj < 4; nj++)
                    mma_m16n8k8(acc[mi][nj], afr[mi], bfr[nj]);
        }
    }

#pragma unroll
    for (int mi = 0; mi < 4; mi++) {
#pragma unroll
        for (int nj = 0; nj < 4; nj++) {
            int r0 = blockIdx.y * 128 + warp_m * 64 + mi * 16 + g;
            int c0 = blockIdx.x * 128 + warp_n * 32 + nj * 8 + 2 * t;
            *(float2*)(C + (size_t)r0 * N + c0) = make_float2(acc[mi][nj][0], acc[mi][nj][1]);
            *(float2*)(C + (size_t)(r0 + 8) * N + c0) = make_float2(acc[mi][nj][2], acc[mi][nj][3]);
        }
    }
}

// ---------------------------------------------------------------------------
// RoPE + tf32 round, all 48 heads (q,k: rope+round; v: round only).
// ---------------------------------------------------------------------------
__global__ void rope_kernel(float* __restrict__ qkv,
                            const float* __restrict__ cosp,
                            const float* __restrict__ sinp)
{
    const int tk = blockIdx.x;
    const int hh = blockIdx.y;        // 0..47
    const int d = threadIdx.x;        // 0..63
    const int s = tk & (SEQ - 1);

    float* p = qkv + (size_t)tk * NQKV + hh * HD;
    float x1 = p[d];
    float x2 = p[d + 64];
    if (hh < 2 * NH) {
        float c1 = cosp[s * HD + d];
        float c2 = cosp[s * HD + d + 64];
        float s1 = sinp[s * HD + d];
        float s2 = sinp[s * HD + d + 64];
        p[d]      = rnd_tf32(x1 * c1 - x2 * s1);
        p[d + 64] = rnd_tf32(x2 * c2 + x1 * s2);
    } else {
        p[d]      = rnd_tf32(x1);
        p[d + 64] = rnd_tf32(x2);
    }
}

// ---------------------------------------------------------------------------
// Flash attention, tf32 mma, BQ=BKV=64, double-buffered cp.async K/V.
// ---------------------------------------------------------------------------
#define QSTR 132
#define SSTR 68
#define NTILE (SEQ / 64)
#define FLASH_SMEM ((64*QSTR*5 + 64*SSTR) * 4 + 64*3*4)

__global__ __launch_bounds__(256) void flash_tf32(
    const float* __restrict__ qkv, float* __restrict__ out)
{
    extern __shared__ unsigned sh[];
    unsigned* Qs = sh;                        // [64][QSTR]
    unsigned* Kb = Qs + 64 * QSTR;            // 2 x [64][QSTR]
    unsigned* Vb = Kb + 2 * 64 * QSTR;        // 2 x [64][QSTR]
    unsigned* Sm = Vb + 2 * 64 * QSTR;        // [64][SSTR]
    float* mS = (float*)(Sm + 64 * SSTR);
    float* lS = mS + 64;
    float* aS = lS + 64;

    const int tid = threadIdx.x;
    const int wid = tid >> 5;
    const int lane = tid & 31;
    const int g = lane >> 2;
    const int t = lane & 3;

    const int b = blockIdx.y >> 4;
    const int h = blockIdx.y & 15;
    const int q0 = blockIdx.x * 64;
    const float scale = 0.08838834764831845f;  // 1/sqrt(128)

    const float* qbase = qkv + (size_t)(b * SEQ + q0) * NQKV + h * HD;
    const float* kbase = qkv + (size_t)(b * SEQ) * NQKV + (NH + h) * HD;
    const float* vbase = qkv + (size_t)(b * SEQ) * NQKV + (2 * NH + h) * HD;

    // load Q raw (pre-rounded tf32 bits)
#pragma unroll 2
    for (int i = tid; i < 64 * 32; i += 256) {
        int r = i >> 5, c4 = (i & 31) * 4;
        *(uint4*)&Qs[r * QSTR + c4] = *(const uint4*)(qbase + (size_t)r * NQKV + c4);
    }
    if (tid < 64) { mS[tid] = -INFINITY; lS[tid] = 0.f; }

    float oacc[2][4][4];
#pragma unroll
    for (int mi = 0; mi < 2; mi++)
#pragma unroll
        for (int nj = 0; nj < 4; nj++)
#pragma unroll
            for (int r = 0; r < 4; r++) oacc[mi][nj][r] = 0.f;

    const int sm_rb = (wid >> 1) * 16;
    const int sm_cb = (wid & 1) * 32;
    const int pm = wid >> 2;
    const int pn = wid & 3;

    const int lr = tid >> 5;            // load row base 0..7 (x8)
    const int lc4 = (tid & 31) * 4;     // load col

#define FLASH_ISSUE(buf, base, kt)                                               \
    do {                                                                         \
        _Pragma("unroll")                                                        \
        for (int p = 0; p < 8; p++) {                                            \
            int r_ = lr + p * 8;                                                 \
            cp16(&(buf)[r_ * QSTR + lc4],                                        \
                 (base) + (size_t)((kt) * 64 + r_) * NQKV + lc4);                \
        }                                                                        \
    } while (0)

    // prologue: K0, V0
    FLASH_ISSUE(Kb, kbase, 0); cp_commit();
    FLASH_ISSUE(Vb, vbase, 0); cp_commit();

    for (int kt = 0; kt < NTILE; kt++) {
        const int cur = (kt & 1) * 64 * QSTR;
        const int nxt = ((kt + 1) & 1) * 64 * QSTR;

        cp_wait<1>();          // K[kt] ready
        __syncthreads();

        // ---- S = Q K^T (raw scores) ----
        {
            const unsigned* Ks = Kb + cur;
            float sacc[4][4];
#pragma unroll
            for (int nj = 0; nj < 4; nj++)
#pragma unroll
                for (int r = 0; r < 4; r++) sacc[nj][r] = 0.f;

#pragma unroll
            for (int ks = 0; ks < 16; ks++) {
                const int kk = ks * 8;
                unsigned qa[4], kbf[4][2];
                qa[0] = Qs[(sm_rb + g) * QSTR + kk + t];
                qa[1] = Qs[(sm_rb + g + 8) * QSTR + kk + t];
                qa[2] = Qs[(sm_rb + g) * QSTR + kk + t + 4];
                qa[3] = Qs[(sm_rb + g + 8) * QSTR + kk + t + 4];
#pragma unroll
                for (int nj = 0; nj < 4; nj++) {
                    int cb = sm_cb + nj * 8;
                    kbf[nj][0] = Ks[(cb + g) * QSTR + kk + t];
                    kbf[nj][1] = Ks[(cb + g) * QSTR + kk + t + 4];
                }
#pragma unroll
                for (int nj = 0; nj < 4; nj++)
                    mma_m16n8k8(sacc[nj], qa, kbf[nj]);
            }
#pragma unroll
            for (int nj = 0; nj < 4; nj++) {
                int col = sm_cb + nj * 8 + 2 * t;
                Sm[(sm_rb + g) * SSTR + col]         = __float_as_uint(sacc[nj][0]);
                Sm[(sm_rb + g) * SSTR + col + 1]     = __float_as_uint(sacc[nj][1]);
                Sm[(sm_rb + g + 8) * SSTR + col]     = __float_as_uint(sacc[nj][2]);
                Sm[(sm_rb + g + 8) * SSTR + col + 1] = __float_as_uint(sacc[nj][3]);
            }
        }

        // overlap: prefetch K[kt+1]
        if (kt + 1 < NTILE) FLASH_ISSUE(Kb + nxt, kbase, kt + 1);
        cp_commit();
        __syncthreads();

        // ---- online softmax (scale folded in) ----
        {
            const int row = tid >> 2;
            const int part = tid & 3;
            float mold = mS[row];
            float vals[16];
            float mloc = -INFINITY;
#pragma unroll
            for (int j = 0; j < 16; j++) {
                vals[j] = __uint_as_float(Sm[row * SSTR + part * 16 + j]) * scale;
                mloc = fmaxf(mloc, vals[j]);
            }
            mloc = fmaxf(mloc, __shfl_xor_sync(0xffffffffu, mloc, 1));
            mloc = fmaxf(mloc, __shfl_xor_sync(0xffffffffu, mloc, 2));
            float mnew = fmaxf(mold, mloc);
            float alpha = __expf(mold - mnew);
            float ps = 0.f;
#pragma unroll
            for (int j = 0; j < 16; j++) {
                float p = __expf(vals[j] - mnew);
                ps += p;
                Sm[row * SSTR + part * 16 + j] = cvt_tf32(p);
            }
            ps += __shfl_xor_sync(0xffffffffu, ps, 1);
            ps += __shfl_xor_sync(0xffffffffu, ps, 2);
            if (part == 0) {
                mS[row] = mnew;
                lS[row] = lS[row] * alpha + ps;
                aS[row] = alpha;
            }
        }

        cp_wait<1>();          // V[kt] ready
        __syncthreads();

        // ---- rescale O, then O += P V ----
        {
            const unsigned* Vs = Vb + cur;
#pragma unroll
            for (int mi = 0; mi < 2; mi++) {
                int r0 = pm * 32 + mi * 16 + g;
                float al0 = aS[r0];
                float al1 = aS[r0 + 8];
#pragma unroll
                for (int nj = 0; nj < 4; nj++) {
                    oacc[mi][nj][0] *= al0;
                    oacc[mi][nj][1] *= al0;
                    oacc[mi][nj][2] *= al1;
                    oacc[mi][nj][3] *= al1;
                }
            }
#pragma unroll
            for (int ks = 0; ks < 8; ks++) {
                const int kk = ks * 8;
                unsigned pa[2][4], vbf[4][2];
#pragma unroll
                for (int mi = 0; mi < 2; mi++) {
                    int rb = pm * 32 + mi * 16;
                    pa[mi][0] = Sm[(rb + g) * SSTR + kk + t];
                    pa[mi][1] = Sm[(rb + g + 8) * SSTR + kk + t];
                    pa[mi][2] = Sm[(rb + g) * SSTR + kk + t + 4];
                    pa[mi][3] = Sm[(rb + g + 8) * SSTR + kk + t + 4];
                }
#pragma unroll
                for (int nj = 0; nj < 4; nj++) {
                    int cb = pn * 32 + nj * 8;
                    vbf[nj][0] = Vs[(kk + t) * QSTR + cb + g];
                    vbf[nj][1] = Vs[(kk + t + 4) * QSTR + cb + g];
                }
#pragma unroll
                for (int mi = 0; mi < 2; mi++)
#pragma unroll
                    for (int nj = 0; nj < 4; nj++)
                        mma_m16n8k8(oacc[mi][nj], pa[mi], vbf[nj]);
            }
        }

        // overlap: prefetch V[kt+1]
        if (kt + 1 < NTILE) FLASH_ISSUE(Vb + nxt, vbase, kt + 1);
        cp_commit();
    }

    // ---- epilogue: normalize + tf32-round + write ----
#pragma unroll
    for (int mi = 0; mi < 2; mi++) {
        int r0 = pm * 32 + mi * 16 + g;
        float li0 = 1.0f / lS[r0];
        float li1 = 1.0f / lS[r0 + 8];
#pragma unroll
        for (int nj = 0; nj < 4; nj++) {
            int col = pn * 32 + nj * 8 + 2 * t;
            float* o0 = out + (size_t)(b * SEQ + q0 + r0) * (NH * HD) + h * HD + col;
            float* o1 = out + (size_t)(b * SEQ + q0 + r0 + 8) * (NH * HD) + h * HD + col;
            *(float2*)o0 = make_float2(rnd_tf32(oacc[mi][nj][0] * li0), rnd_tf32(oacc[mi][nj][1] * li0));
            *(float2*)o1 = make_float2(rnd_tf32(oacc[mi][nj][2] * li1), rnd_tf32(oacc[mi][nj][3] * li1));
        }
    }
}

// ---------------------------------------------------------------------------
extern "C" void kernel_launch(void* const* d_in, const int* in_sizes, int n_in,
                              void* d_out, int out_size)
{
    const float* hidden = (const float*)d_in[0];
    const float* cosp   = (const float*)d_in[1];
    const float* sinp   = (const float*)d_in[2];
    const float* wqkv   = (const float*)d_in[3];
    const float* wo     = (const float*)d_in[4];
    float* out = (float*)d_out;

    void *p0, *p1, *p2, *p3, *p4;
    cudaGetSymbolAddress(&p0, g_qkv);
    cudaGetSymbolAddress(&p1, g_attn);
    cudaGetSymbolAddress(&p2, g_hid_t);
    cudaGetSymbolAddress(&p3, g_wqkv_t);
    cudaGetSymbolAddress(&p4, g_wo_t);
    float* qkv   = (float*)p0;
    float* attn  = (float*)p1;
    float* hid_t = (float*)p2;
    float* wqkv_t= (float*)p3;
    float* wo_t  = (float*)p4;

    static bool attr_set = false;
    if (!attr_set) {
        cudaFuncSetAttribute(flash_tf32, cudaFuncAttributeMaxDynamicSharedMemorySize, FLASH_SMEM);
        cudaFuncSetAttribute(gemm_tf32, cudaFuncAttributeMaxDynamicSharedMemorySize, GEMM_SMEM);
        attr_set = true;
    }

    // 0) tf32 pre-rounding of GEMM operands
    {
        int n4h = NTOK * DM / 4;
        round_tf32_kernel<<<n4h / 256, 256>>>((const float4*)hidden, (float4*)hid_t, n4h);
        int n4q = DM * NQKV / 4;
        round_tf32_kernel<<<n4q / 256, 256>>>((const float4*)wqkv, (float4*)wqkv_t, n4q);
        int n4o = DM * DM / 4;
        round_tf32_kernel<<<n4o / 256, 256>>>((const float4*)wo, (float4*)wo_t, n4o);
    }
    // 1) QKV projection
    {
        dim3 grid(NQKV / 128, NTOK / 128);
        gemm_tf32<<<grid, 256, GEMM_SMEM>>>(hid_t, wqkv_t, qkv, NTOK, NQKV, DM);
    }
    // 2) RoPE + rounding (q,k rope; v round)
    {
        dim3 grid(NTOK, 3 * NH);
        rope_kernel<<<grid, 64>>>(qkv, cosp, sinp);
    }
    // 3) Flash attention
    {
        dim3 grid(SEQ / 64, BATCH * NH);
        flash_tf32<<<grid, 256, FLASH_SMEM>>>(qkv, attn);
    }
    // 4) Output projection
    {
        dim3 grid(DM / 128, NTOK / 128);
        gemm_tf32<<<grid, 256, GEMM_SMEM>>>(attn, wo_t, out, NTOK, DM, NH * HD);
    }
}

// round 5
// speedup vs baseline: 4.9064x; 1.1089x over previous
#include <cuda_runtime.h>
#include <math.h>
#include <stdint.h>

// Problem constants
#define BATCH 2
#define SEQ 2048
#define DM 2048
#define NH 16
#define HD 128
#define NQKV ((NH + 2*NH) * HD)   // 6144
#define NTOK (BATCH * SEQ)        // 4096

// Scratch (allocation-free rule: __device__ globals)
__device__ float g_qkv[(size_t)NTOK * NQKV];        // 96 MB
__device__ float g_attn[(size_t)NTOK * (NH * HD)];  // 32 MB
__device__ float g_hid_t[(size_t)NTOK * DM];        // 32 MB
__device__ float g_wqkv_t[(size_t)DM * NQKV];       // 48 MB
__device__ float g_wo_t[(size_t)DM * DM];           // 16 MB

// ---------------------------------------------------------------------------
// helpers
// ---------------------------------------------------------------------------
__device__ __forceinline__ unsigned cvt_tf32(float x) {
    unsigned u;
    asm("cvt.rna.tf32.f32 %0, %1;" : "=r"(u) : "f"(x));
    return u;
}
__device__ __forceinline__ float rnd_tf32(float x) {
    return __uint_as_float(cvt_tf32(x));
}

__device__ __forceinline__ void mma_m16n8k8(float* c, const unsigned* a, const unsigned* b) {
    asm volatile(
        "mma.sync.aligned.m16n8k8.row.col.f32.tf32.tf32.f32 "
        "{%0,%1,%2,%3}, {%4,%5,%6,%7}, {%8,%9}, {%0,%1,%2,%3};"
        : "+f"(c[0]), "+f"(c[1]), "+f"(c[2]), "+f"(c[3])
        : "r"(a[0]), "r"(a[1]), "r"(a[2]), "r"(a[3]), "r"(b[0]), "r"(b[1]));
}

__device__ __forceinline__ void cp16(void* dst_smem, const void* src) {
    unsigned d = (unsigned)__cvta_generic_to_shared(dst_smem);
    asm volatile("cp.async.cg.shared.global [%0], [%1], 16;" :: "r"(d), "l"(src));
}
__device__ __forceinline__ void cp_commit() {
    asm volatile("cp.async.commit_group;");
}
template<int N>
__device__ __forceinline__ void cp_wait() {
    asm volatile("cp.async.wait_group %0;" :: "n"(N));
}

// ---------------------------------------------------------------------------
// tf32 pre-rounding (vectorized)
// ---------------------------------------------------------------------------
__global__ void round_tf32_kernel(const float4* __restrict__ in,
                                  float4* __restrict__ out, int n4)
{
    int i = blockIdx.x * 256 + threadIdx.x;
    if (i < n4) {
        float4 v = in[i];
        out[i] = make_float4(rnd_tf32(v.x), rnd_tf32(v.y), rnd_tf32(v.z), rnd_tf32(v.w));
    }
}

// ---------------------------------------------------------------------------
// TF32 GEMM (R3 known-good): C = A*B, 128x128x32, cp.async 3-stage, 2 CTA/SM
// ---------------------------------------------------------------------------
#define ASTR 36
#define BSTR 136
#define STG_W (128*ASTR + 32*BSTR)
#define GEMM_SMEM (3 * STG_W * 4)

__global__ __launch_bounds__(256, 2) void gemm_tf32(
    const float* __restrict__ A, const float* __restrict__ B,
    float* __restrict__ C, int M, int N, int K)
{
    extern __shared__ float sm[];

    const int tid = threadIdx.x;
    const int wid = tid >> 5;
    const int lane = tid & 31;
    const int g = lane >> 2;
    const int t = lane & 3;
    const int warp_m = wid & 1;
    const int warp_n = wid >> 1;

    const float* Ab = A + (size_t)(blockIdx.y * 128) * K;
    const float* Bb = B + (size_t)(blockIdx.x * 128);

    const int arow = tid >> 3;
    const int acol = (tid & 7) * 4;
    const int brow = tid >> 5;
    const int bcol = (tid & 31) * 4;

    float acc[4][4][4];
#pragma unroll
    for (int mi = 0; mi < 4; mi++)
#pragma unroll
        for (int nj = 0; nj < 4; nj++)
#pragma unroll
            for (int r = 0; r < 4; r++) acc[mi][nj][r] = 0.f;

    const int KT = K >> 5;

#define GEMM_ISSUE(stage, kt)                                                       \
    do {                                                                            \
        float* as_ = sm + (stage) * STG_W;                                          \
        float* bs_ = as_ + 128 * ASTR;                                              \
        int k0_ = (kt) * 32;                                                        \
        _Pragma("unroll")                                                           \
        for (int p = 0; p < 4; p++) {                                               \
            cp16(&as_[(arow + p * 32) * ASTR + acol],                               \
                 Ab + (size_t)(arow + p * 32) * K + k0_ + acol);                    \
            cp16(&bs_[(brow + p * 8) * BSTR + bcol],                                \
                 Bb + (size_t)(k0_ + brow + p * 8) * N + bcol);                     \
        }                                                                           \
    } while (0)

    GEMM_ISSUE(0, 0); cp_commit();
    GEMM_ISSUE(1, 1); cp_commit();

    for (int kt = 0; kt < KT; kt++) {
        cp_wait<1>();
        __syncthreads();

        if (kt + 2 < KT) GEMM_ISSUE((kt + 2) % 3, kt + 2);
        cp_commit();

        const float* as = sm + (kt % 3) * STG_W;
        const float* bs = as + 128 * ASTR;

#pragma unroll
        for (int ks = 0; ks < 4; ks++) {
            const int kk = ks * 8;
            unsigned afr[4][4], bfr[4][2];
#pragma unroll
            for (int mi = 0; mi < 4; mi++) {
                int rb = warp_m * 64 + mi * 16;
                afr[mi][0] = __float_as_uint(as[(rb + g) * ASTR + kk + t]);
                afr[mi][1] = __float_as_uint(as[(rb + g + 8) * ASTR + kk + t]);
                afr[mi][2] = __float_as_uint(as[(rb + g) * ASTR + kk + t + 4]);
                afr[mi][3] = __float_as_uint(as[(rb + g + 8) * ASTR + kk + t + 4]);
            }
#pragma unroll
            for (int nj = 0; nj < 4; nj++) {
                int cb = warp_n * 32 + nj * 8;
                bfr[nj][0] = __float_as_uint(bs[(kk + t) * BSTR + cb + g]);
                bfr[nj][1] = __float_as_uint(bs[(kk + t + 4) * BSTR + cb + g]);
            }
#pragma unroll
            for (int mi = 0; mi < 4; mi++)
#pragma unroll
                for (int nj = 0; nj < 4; nj++)
                    mma_m16n8k8(acc[mi][nj], afr[mi], bfr[nj]);
        }
    }

#pragma unroll
    for (int mi = 0; mi < 4; mi++) {
#pragma unroll
        for (int nj = 0; nj < 4; nj++) {
            int r0 = blockIdx.y * 128 + warp_m * 64 + mi * 16 + g;
            int c0 = blockIdx.x * 128 + warp_n * 32 + nj * 8 + 2 * t;
            *(float2*)(C + (size_t)r0 * N + c0) = make_float2(acc[mi][nj][0], acc[mi][nj][1]);
            *(float2*)(C + (size_t)(r0 + 8) * N + c0) = make_float2(acc[mi][nj][2], acc[mi][nj][3]);
        }
    }
}

// ---------------------------------------------------------------------------
// RoPE + tf32 round, all 48 heads (q,k: rope+round; v: round only).
// ---------------------------------------------------------------------------
__global__ void rope_kernel(float* __restrict__ qkv,
                            const float* __restrict__ cosp,
                            const float* __restrict__ sinp)
{
    const int tk = blockIdx.x;
    const int hh = blockIdx.y;        // 0..47
    const int d = threadIdx.x;        // 0..63
    const int s = tk & (SEQ - 1);

    float* p = qkv + (size_t)tk * NQKV + hh * HD;
    float x1 = p[d];
    float x2 = p[d + 64];
    if (hh < 2 * NH) {
        float c1 = cosp[s * HD + d];
        float c2 = cosp[s * HD + d + 64];
        float s1 = sinp[s * HD + d];
        float s2 = sinp[s * HD + d + 64];
        p[d]      = rnd_tf32(x1 * c1 - x2 * s1);
        p[d + 64] = rnd_tf32(x2 * c2 + x1 * s2);
    } else {
        p[d]      = rnd_tf32(x1);
        p[d + 64] = rnd_tf32(x2);
    }
}

// ---------------------------------------------------------------------------
// Flash attention v2-style: register-resident P, warp-local softmax.
// BQ=128 (8 warps x 16 rows), BKV=64, HD=128, cp.async double-buffered K/V.
// ---------------------------------------------------------------------------
#define F2_STR 132
#define F2_BUF (64 * F2_STR)
#define FLASH2_SMEM (4 * F2_BUF * 4)   // 135168 bytes
#define NTILE2 (SEQ / 64)

__global__ __launch_bounds__(256, 1) void flash2_tf32(
    const float* __restrict__ qkv, float* __restrict__ out)
{
    extern __shared__ float sf[];
    // buffers: K0 = sf, K1 = sf+F2_BUF, V0 = sf+2*F2_BUF, V1 = sf+3*F2_BUF

    const int tid = threadIdx.x;
    const int wid = tid >> 5;
    const int lane = tid & 31;
    const int g = lane >> 2;
    const int t = lane & 3;
    const unsigned FULL = 0xffffffffu;

    const int b = blockIdx.y >> 4;
    const int h = blockIdx.y & 15;
    const int q0 = blockIdx.x * 128;
    const float scale = 0.08838834764831845f;  // 1/sqrt(128)

    const float* qbase = qkv + (size_t)(b * SEQ + q0) * NQKV + h * HD;
    const float* kbase = qkv + (size_t)(b * SEQ) * NQKV + (NH + h) * HD;
    const float* vbase = qkv + (size_t)(b * SEQ) * NQKV + (2 * NH + h) * HD;

    // ---- stage Q (128x128) into smem, then read fragments to registers ----
    for (int i = tid; i < 128 * 32; i += 256) {
        int r = i >> 5, c4 = (i & 31) * 4;
        cp16(&sf[r * F2_STR + c4], qbase + (size_t)r * NQKV + c4);
    }
    cp_commit(); cp_wait<0>();
    __syncthreads();

    unsigned qa[16][4];
    {
        const float* Qw = sf + (wid * 16) * F2_STR;
#pragma unroll
        for (int ks = 0; ks < 16; ks++) {
            int kk = ks * 8;
            qa[ks][0] = __float_as_uint(Qw[(g    ) * F2_STR + kk + t]);
            qa[ks][1] = __float_as_uint(Qw[(g + 8) * F2_STR + kk + t]);
            qa[ks][2] = __float_as_uint(Qw[(g    ) * F2_STR + kk + t + 4]);
            qa[ks][3] = __float_as_uint(Qw[(g + 8) * F2_STR + kk + t + 4]);
        }
    }
    __syncthreads();   // staging area becomes K buffers

    float oacc[16][4];
#pragma unroll
    for (int ni = 0; ni < 16; ni++)
#pragma unroll
        for (int r = 0; r < 4; r++) oacc[ni][r] = 0.f;

    float m0 = -INFINITY, m1 = -INFINITY, l0 = 0.f, l1 = 0.f;

    const int lr = tid >> 5;           // load row base (0..7, step 8)
    const int lc4 = (tid & 31) * 4;    // load col

#define F2_ISSUE(buf, base, kt)                                                  \
    do {                                                                         \
        _Pragma("unroll")                                                        \
        for (int p_ = 0; p_ < 8; p_++) {                                         \
            int r_ = lr + p_ * 8;                                                \
            cp16(&(buf)[r_ * F2_STR + lc4],                                      \
                 (base) + (size_t)((kt) * 64 + r_) * NQKV + lc4);                \
        }                                                                        \
    } while (0)

    F2_ISSUE(sf, kbase, 0); cp_commit();
    F2_ISSUE((sf + 2 * F2_BUF), vbase, 0); cp_commit();

    for (int kt = 0; kt < NTILE2; kt++) {
        const float* Ks = sf + (kt & 1) * F2_BUF;
        const float* Vs = sf + (2 + (kt & 1)) * F2_BUF;
        float* Kn = sf + ((kt + 1) & 1) * F2_BUF;
        float* Vn = sf + (2 + ((kt + 1) & 1)) * F2_BUF;

        cp_wait<1>();          // K[kt] ready
        __syncthreads();

        // ---- S = Q K^T (16 rows x 64 cols per warp) ----
        float sacc[8][4];
#pragma unroll
        for (int nj = 0; nj < 8; nj++)
#pragma unroll
            for (int r = 0; r < 4; r++) sacc[nj][r] = 0.f;

#pragma unroll
        for (int ks = 0; ks < 16; ks++) {
            const int kk = ks * 8;
#pragma unroll
            for (int nj = 0; nj < 8; nj++) {
                unsigned kb[2];
                kb[0] = __float_as_uint(Ks[(nj * 8 + g) * F2_STR + kk + t]);
                kb[1] = __float_as_uint(Ks[(nj * 8 + g) * F2_STR + kk + t + 4]);
                mma_m16n8k8(sacc[nj], qa[ks], kb);
            }
        }

        if (kt + 1 < NTILE2) F2_ISSUE(Kn, kbase, kt + 1);
        cp_commit();

        // ---- warp-local online softmax (rows g and g+8) ----
        float mx0 = -INFINITY, mx1 = -INFINITY;
#pragma unroll
        for (int j = 0; j < 8; j++) {
            sacc[j][0] *= scale; sacc[j][1] *= scale;
            sacc[j][2] *= scale; sacc[j][3] *= scale;
            mx0 = fmaxf(mx0, fmaxf(sacc[j][0], sacc[j][1]));
            mx1 = fmaxf(mx1, fmaxf(sacc[j][2], sacc[j][3]));
        }
        mx0 = fmaxf(mx0, __shfl_xor_sync(FULL, mx0, 1));
        mx0 = fmaxf(mx0, __shfl_xor_sync(FULL, mx0, 2));
        mx1 = fmaxf(mx1, __shfl_xor_sync(FULL, mx1, 1));
        mx1 = fmaxf(mx1, __shfl_xor_sync(FULL, mx1, 2));
        float mn0 = fmaxf(m0, mx0), mn1 = fmaxf(m1, mx1);
        float a0 = __expf(m0 - mn0), a1 = __expf(m1 - mn1);
        float s0 = 0.f, s1 = 0.f;
#pragma unroll
        for (int j = 0; j < 8; j++) {
            float p00 = __expf(sacc[j][0] - mn0);
            float p01 = __expf(sacc[j][1] - mn0);
            float p10 = __expf(sacc[j][2] - mn1);
            float p11 = __expf(sacc[j][3] - mn1);
            s0 += p00 + p01;
            s1 += p10 + p11;
            sacc[j][0] = __uint_as_float(cvt_tf32(p00));
            sacc[j][1] = __uint_as_float(cvt_tf32(p01));
            sacc[j][2] = __uint_as_float(cvt_tf32(p10));
            sacc[j][3] = __uint_as_float(cvt_tf32(p11));
        }
        s0 += __shfl_xor_sync(FULL, s0, 1);
        s0 += __shfl_xor_sync(FULL, s0, 2);
        s1 += __shfl_xor_sync(FULL, s1, 1);
        s1 += __shfl_xor_sync(FULL, s1, 2);
        l0 = l0 * a0 + s0;
        l1 = l1 * a1 + s1;
        m0 = mn0; m1 = mn1;
#pragma unroll
        for (int ni = 0; ni < 16; ni++) {
            oacc[ni][0] *= a0; oacc[ni][1] *= a0;
            oacc[ni][2] *= a1; oacc[ni][3] *= a1;
        }

        cp_wait<1>();          // V[kt] ready
        __syncthreads();

        // ---- O += P V : P C-frags -> A-frags via quad shuffles ----
        const int sl = (lane & ~3) | (t >> 1);
#pragma unroll
        for (int j = 0; j < 8; j++) {
            float x0  = __shfl_sync(FULL, sacc[j][0], sl);
            float x1  = __shfl_sync(FULL, sacc[j][1], sl);
            float y0  = __shfl_sync(FULL, sacc[j][2], sl);
            float y1  = __shfl_sync(FULL, sacc[j][3], sl);
            float x0b = __shfl_sync(FULL, sacc[j][0], sl + 2);
            float x1b = __shfl_sync(FULL, sacc[j][1], sl + 2);
            float y0b = __shfl_sync(FULL, sacc[j][2], sl + 2);
            float y1b = __shfl_sync(FULL, sacc[j][3], sl + 2);
            unsigned pa[4];
            pa[0] = __float_as_uint((t & 1) ? x1  : x0);
            pa[1] = __float_as_uint((t & 1) ? y1  : y0);
            pa[2] = __float_as_uint((t & 1) ? x1b : x0b);
            pa[3] = __float_as_uint((t & 1) ? y1b : y0b);
#pragma unroll
            for (int ni = 0; ni < 16; ni++) {
                unsigned vbf[2];
                vbf[0] = __float_as_uint(Vs[(j * 8 + t) * F2_STR + ni * 8 + g]);
                vbf[1] = __float_as_uint(Vs[(j * 8 + t + 4) * F2_STR + ni * 8 + g]);
                mma_m16n8k8(oacc[ni], pa, vbf);
            }
        }

        if (kt + 1 < NTILE2) F2_ISSUE(Vn, vbase, kt + 1);
        cp_commit();
    }

    // ---- epilogue: normalize + tf32-round + write ----
    float li0 = 1.0f / l0, li1 = 1.0f / l1;
    const int r0 = q0 + wid * 16 + g;
    float* o0 = out + (size_t)(b * SEQ + r0) * (NH * HD) + h * HD;
    float* o1 = out + (size_t)(b * SEQ + r0 + 8) * (NH * HD) + h * HD;
#pragma unroll
    for (int ni = 0; ni < 16; ni++) {
        int nc = ni * 8 + 2 * t;
        *(float2*)(o0 + nc) = make_float2(rnd_tf32(oacc[ni][0] * li0),
                                          rnd_tf32(oacc[ni][1] * li0));
        *(float2*)(o1 + nc) = make_float2(rnd_tf32(oacc[ni][2] * li1),
                                          rnd_tf32(oacc[ni][3] * li1));
    }
}

// ---------------------------------------------------------------------------
extern "C" void kernel_launch(void* const* d_in, const int* in_sizes, int n_in,
                              void* d_out, int out_size)
{
    const float* hidden = (const float*)d_in[0];
    const float* cosp   = (const float*)d_in[1];
    const float* sinp   = (const float*)d_in[2];
    const float* wqkv   = (const float*)d_in[3];
    const float* wo     = (const float*)d_in[4];
    float* out = (float*)d_out;

    void *p0, *p1, *p2, *p3, *p4;
    cudaGetSymbolAddress(&p0, g_qkv);
    cudaGetSymbolAddress(&p1, g_attn);
    cudaGetSymbolAddress(&p2, g_hid_t);
    cudaGetSymbolAddress(&p3, g_wqkv_t);
    cudaGetSymbolAddress(&p4, g_wo_t);
    float* qkv    = (float*)p0;
    float* attn   = (float*)p1;
    float* hid_t  = (float*)p2;
    float* wqkv_t = (float*)p3;
    float* wo_t   = (float*)p4;

    static bool attr_set = false;
    if (!attr_set) {
        cudaFuncSetAttribute(flash2_tf32, cudaFuncAttributeMaxDynamicSharedMemorySize, FLASH2_SMEM);
        cudaFuncSetAttribute(gemm_tf32, cudaFuncAttributeMaxDynamicSharedMemorySize, GEMM_SMEM);
        attr_set = true;
    }

    // 0) tf32 pre-rounding of GEMM operands
    {
        int n4h = NTOK * DM / 4;
        round_tf32_kernel<<<n4h / 256, 256>>>((const float4*)hidden, (float4*)hid_t, n4h);
        int n4q = DM * NQKV / 4;
        round_tf32_kernel<<<n4q / 256, 256>>>((const float4*)wqkv, (float4*)wqkv_t, n4q);
        int n4o = DM * DM / 4;
        round_tf32_kernel<<<n4o / 256, 256>>>((const float4*)wo, (float4*)wo_t, n4o);
    }
    // 1) QKV projection
    {
        dim3 grid(NQKV / 128, NTOK / 128);
        gemm_tf32<<<grid, 256, GEMM_SMEM>>>(hid_t, wqkv_t, qkv, NTOK, NQKV, DM);
    }
    // 2) RoPE + rounding
    {
        dim3 grid(NTOK, 3 * NH);
        rope_kernel<<<grid, 64>>>(qkv, cosp, sinp);
    }
    // 3) Flash attention (FA2-style, register P)
    {
        dim3 grid(SEQ / 128, BATCH * NH);   // 16 x 32
        flash2_tf32<<<grid, 256, FLASH2_SMEM>>>(qkv, attn);
    }
    // 4) Output projection
    {
        dim3 grid(DM / 128, NTOK / 128);
        gemm_tf32<<<grid, 256, GEMM_SMEM>>>(attn, wo_t, out, NTOK, DM, NH * HD);
    }
}